// round 13
// baseline (speedup 1.0000x reference)
#include <cuda_runtime.h>
#include <cuda_fp16.h>
#include <math.h>
#include <stdint.h>

#define Bq   8
#define Lq   1024
#define DM   512
#define DIN  1024
#define DFF  2048
#define DS   16
#define DTR  32
#define MROWS (Bq*Lq)   /* 8192 token rows */

typedef __half h16;

// ---------------- fp32 scratch ----------------
__device__ float g_xdbl1[MROWS*64];
__device__ float g_xdbl2[MROWS*64];
__device__ float g_o   [MROWS*DM];
__device__ float g_xln [MROWS*DM];
__device__ float g_yff [MROWS*DM];
__device__ float g_A   [2*DIN*DS];     // -exp(Alog) * log2(e)

// ---------------- fp16 activations ----------------
__device__ h16 g_xz1h[MROWS*2*DIN];    // in_proj out, dir0: [xs | z]
__device__ h16 g_xz2h[MROWS*2*DIN];
__device__ h16 g_xh  [MROWS*DM];
__device__ h16 g_xc1h[MROWS*DIN];
__device__ h16 g_xc2h[MROWS*DIN];
__device__ h16 g_dt1h[MROWS*DIN];
__device__ h16 g_dt2h[MROWS*DIN];
__device__ h16 g_yh  [MROWS*2*DIN];    // [dir0 | dir1] per row
__device__ h16 g_xlnh[MROWS*DM];
__device__ h16 g_hffh[MROWS*DFF];

// ---------------- fp16 weights ----------------
__device__ h16 g_win1h[2*DIN*DM];
__device__ h16 g_win2h[2*DIN*DM];
__device__ h16 g_wxp1h[64*DIN];
__device__ h16 g_wxp2h[64*DIN];
__device__ h16 g_woh  [DM*2*DIN];      // fused [out1 | out2]
__device__ h16 g_wc1h [DFF*DM];
__device__ h16 g_wc2h [DM*DFF];

// ======================= helpers =======================
__device__ __forceinline__ float ex2(float x) {
    float r;
    asm("ex2.approx.f32 %0, %1;" : "=f"(r) : "f"(x));
    return r;
}
__device__ __forceinline__ uint32_t smem_u32(const void* p) {
    uint32_t a;
    asm("{ .reg .u64 t; cvta.to.shared.u64 t, %1; cvt.u32.u64 %0, t; }" : "=r"(a) : "l"(p));
    return a;
}
__device__ __forceinline__ void ldmx4(uint32_t* r, uint32_t addr) {
    asm volatile("ldmatrix.sync.aligned.m8n8.x4.shared.b16 {%0,%1,%2,%3}, [%4];"
                 : "=r"(r[0]), "=r"(r[1]), "=r"(r[2]), "=r"(r[3]) : "r"(addr));
}
__device__ __forceinline__ void ldmx2(uint32_t* r, uint32_t addr) {
    asm volatile("ldmatrix.sync.aligned.m8n8.x2.shared.b16 {%0,%1}, [%2];"
                 : "=r"(r[0]), "=r"(r[1]) : "r"(addr));
}
__device__ __forceinline__ void hmma(float* d, const uint32_t* a, const uint32_t* b) {
    asm volatile(
        "mma.sync.aligned.m16n8k16.row.col.f32.f16.f16.f32 "
        "{%0,%1,%2,%3}, {%4,%5,%6,%7}, {%8,%9}, {%0,%1,%2,%3};"
        : "+f"(d[0]), "+f"(d[1]), "+f"(d[2]), "+f"(d[3])
        : "r"(a[0]), "r"(a[1]), "r"(a[2]), "r"(a[3]), "r"(b[0]), "r"(b[1]));
}
__device__ __forceinline__ void cpa16(uint32_t dst, const void* src) {
    asm volatile("cp.async.cg.shared.global [%0], [%1], 16;" :: "r"(dst), "l"(src));
}
#define CP_COMMIT() asm volatile("cp.async.commit_group;" ::: "memory")
template<int N> __device__ __forceinline__ void cp_wait() {
    asm volatile("cp.async.wait_group %0;" :: "n"(N) : "memory");
}
__device__ __forceinline__ float gelu_exact(float x) {
    return 0.5f * x * (1.0f + erff(x * 0.70710678118654752f));
}

struct GArg { const h16* A; const h16* B; float* C; h16* Ch; };

// ======================= fp16 HMMA GEMM, 3-stage cp.async (R6 form) =======================
// C[m,n] = sum_k A[m,k]*B[n,k]; fp16 in, fp32 accum. blockIdx.z selects arg set.
// Block tile 128 x BN, BK=32, warp tile 64x32.
// EPI: 0 = fp32 store, 3 = bias fp32, 4 = bias+GELU fp16, 6 = smem-staged fp16 store.
template<int BN, int EPI>
__global__ __launch_bounds__(64*(BN/32))
void tgemm(GArg g0, GArg g1, int lda, int ldb, int ldc, int K,
           const float* bias0, const float* bias1)
{
    constexpr int WN = BN / 32;
    constexpr int T  = 64 * WN;
    constexpr int PK = 40;                    // padded k stride (elems), 80B
    constexpr int ASZ = 128 * PK * 2;         // bytes
    constexpr int BSZ = BN  * PK * 2;
    constexpr int STG = ASZ + BSZ;

    const GArg ga = blockIdx.z ? g1 : g0;
    const float* bias = blockIdx.z ? bias1 : bias0;

    extern __shared__ char smem[];
    const uint32_t base = smem_u32(smem);

    const int tid  = threadIdx.x;
    const int wid  = tid >> 5, lane = tid & 31;
    const int warp_m = wid & 1, warp_n = wid >> 1;
    const int m0 = blockIdx.y * 128;
    const int n0 = blockIdx.x * BN;

    float acc[4][4][4];
#pragma unroll
    for (int i = 0; i < 4; i++)
#pragma unroll
        for (int j = 0; j < 4; j++)
#pragma unroll
            for (int q = 0; q < 4; q++) acc[i][j][q] = 0.f;

    const int rA = (lane & 15);
    const int cA = (lane >> 4) * 8;
    const int l2 = lane & 15;
    const int rB = l2 & 7;
    const int cB = (l2 >> 3) * 8;

    auto load_tiles = [&](int k0, uint32_t aS, uint32_t bS) {
#pragma unroll
        for (int m = 0; m < 512 / T; m++) {
            int cid = tid + m * T;
            int row = cid >> 2, c4 = cid & 3;
            cpa16(aS + (row * PK + c4 * 8) * 2,
                  ga.A + (size_t)(m0 + row) * lda + k0 + c4 * 8);
        }
#pragma unroll
        for (int m = 0; m < (BN * 4) / T; m++) {
            int cid = tid + m * T;
            int row = cid >> 2, c4 = cid & 3;
            cpa16(bS + (row * PK + c4 * 8) * 2,
                  ga.B + (size_t)(n0 + row) * ldb + k0 + c4 * 8);
        }
    };

    const int nk = K / 32;
    load_tiles(0, base, base + ASZ);
    CP_COMMIT();
    load_tiles(32, base + STG, base + STG + ASZ);
    CP_COMMIT();

    for (int i = 0; i < nk; i++) {
        if (i < nk - 1) cp_wait<1>(); else cp_wait<0>();
        __syncthreads();
        if (i + 2 < nk) {
            int s = (i + 2) % 3;
            load_tiles((i + 2) * 32, base + s * STG, base + s * STG + ASZ);
            CP_COMMIT();
        }
        const uint32_t aS = base + (i % 3) * STG;
        const uint32_t bS = aS + ASZ;

#pragma unroll
        for (int kk = 0; kk < 32; kk += 16) {
            uint32_t Ar[4][4], Br[4][2];
            const int aoff = kk + cA;
            const int boff = kk + cB;
#pragma unroll
            for (int mf = 0; mf < 4; mf++)
                ldmx4(Ar[mf], aS + ((warp_m*64 + mf*16 + rA) * PK + aoff) * 2);
#pragma unroll
            for (int nf = 0; nf < 4; nf++)
                ldmx2(Br[nf], bS + ((warp_n*32 + nf*8 + rB) * PK + boff) * 2);
#pragma unroll
            for (int mf = 0; mf < 4; mf++)
#pragma unroll
                for (int nf = 0; nf < 4; nf++)
                    hmma(acc[mf][nf], Ar[mf], Br[nf]);
        }
    }

    // ---- epilogue ----
    const int rr = lane >> 2;
    const int cc = (lane & 3) * 2;

    if (EPI == 6) {
        // stage fp16 tile in smem, then fully-coalesced 16B global stores
        constexpr int EPK = BN + 8;           // padded halves per row
        h16* ep = (h16*)smem;
        __syncthreads();                       // smem reuse after mainloop
#pragma unroll
        for (int mf = 0; mf < 4; mf++) {
#pragma unroll
            for (int nf = 0; nf < 4; nf++) {
                int col = warp_n*32 + nf*8 + cc;
#pragma unroll
                for (int h = 0; h < 2; h++) {
                    int row = warp_m*64 + mf*16 + rr + h*8;
                    *reinterpret_cast<__half2*>(&ep[row*EPK + col]) =
                        __floats2half2_rn(acc[mf][nf][h*2+0], acc[mf][nf][h*2+1]);
                }
            }
        }
        __syncthreads();
        constexpr int CPR = BN / 8;           // 16B chunks per row
        constexpr int ITER = 128 * CPR / T;
#pragma unroll
        for (int it = 0; it < ITER; it++) {
            int idx = tid + it * T;
            int row = idx / CPR, c8 = idx % CPR;
            uint4 v = *reinterpret_cast<const uint4*>(&ep[row*EPK + c8*8]);
            *reinterpret_cast<uint4*>(ga.Ch + (size_t)(m0 + row) * ldc + n0 + c8*8) = v;
        }
        return;
    }

#pragma unroll
    for (int mf = 0; mf < 4; mf++) {
#pragma unroll
        for (int nf = 0; nf < 4; nf++) {
            int col = n0 + warp_n*32 + nf*8 + cc;
            float b0 = 0.f, b1 = 0.f;
            if (EPI == 3 || EPI == 4) { b0 = bias[col]; b1 = bias[col+1]; }
#pragma unroll
            for (int h = 0; h < 2; h++) {
                int row = m0 + warp_m*64 + mf*16 + rr + h*8;
                float v0 = acc[mf][nf][h*2+0];
                float v1 = acc[mf][nf][h*2+1];
                if (EPI == 3) {
                    *reinterpret_cast<float2*>(ga.C + (size_t)row * ldc + col) =
                        make_float2(v0 + b0, v1 + b1);
                } else if (EPI == 4) {
                    v0 = gelu_exact(v0 + b0); v1 = gelu_exact(v1 + b1);
                    *reinterpret_cast<__half2*>(ga.Ch + (size_t)row * ldc + col) =
                        __floats2half2_rn(v0, v1);
                } else {
                    *reinterpret_cast<float2*>(ga.C + (size_t)row * ldc + col) =
                        make_float2(v0, v1);
                }
            }
        }
    }
}

// ---------------- single launch: all fp32->fp16 conversions ----------------
#define SZ_X   (MROWS*DM)
#define SZ_IN  (2*DIN*DM)
#define SZ_XP  (64*DIN)
#define SZ_OP  (DM*DIN)
#define SZ_C1  (DFF*DM)
#define SZ_C2  (DM*DFF)
#define CV_TOTAL (SZ_X + 2*SZ_IN + 2*SZ_XP + 2*SZ_OP + SZ_C1 + SZ_C2)

__global__ void convert_all(const float* __restrict__ x,
                            const float* __restrict__ in1, const float* __restrict__ in2,
                            const float* __restrict__ xp1, const float* __restrict__ xp2,
                            const float* __restrict__ op1, const float* __restrict__ op2,
                            const float* __restrict__ c1,  const float* __restrict__ c2)
{
    long j = (long)blockIdx.x*256 + threadIdx.x;
    if (j < SZ_X)  { g_xh[j] = __float2half_rn(x[j]); return; }    j -= SZ_X;
    if (j < SZ_IN) { g_win1h[j] = __float2half_rn(in1[j]); return; } j -= SZ_IN;
    if (j < SZ_IN) { g_win2h[j] = __float2half_rn(in2[j]); return; } j -= SZ_IN;
    if (j < SZ_XP) { g_wxp1h[j] = __float2half_rn(xp1[j]); return; } j -= SZ_XP;
    if (j < SZ_XP) { g_wxp2h[j] = __float2half_rn(xp2[j]); return; } j -= SZ_XP;
    if (j < SZ_OP) { long r = j/DIN, k = j%DIN;
                     g_woh[r*2*DIN + k] = __float2half_rn(op1[j]); return; } j -= SZ_OP;
    if (j < SZ_OP) { long r = j/DIN, k = j%DIN;
                     g_woh[r*2*DIN + DIN + k] = __float2half_rn(op2[j]); return; } j -= SZ_OP;
    if (j < SZ_C1) { g_wc1h[j] = __float2half_rn(c1[j]); return; } j -= SZ_C1;
    if (j < SZ_C2) { g_wc2h[j] = __float2half_rn(c2[j]); }
}

// ---------------- prep: A = -exp(Alog) * log2(e) ----------------
__global__ void prep_kernel(const float* __restrict__ Alog1, const float* __restrict__ Alog2)
{
    int i = blockIdx.x*256 + threadIdx.x;
    if (i < DIN*DS) {
        g_A[i]          = -__expf(Alog1[i]) * 1.44269504088896f;
        g_A[DIN*DS + i] = -__expf(Alog2[i]) * 1.44269504088896f;
    }
}

// ---------------- depthwise causal conv (k=4) + bias + SiLU, rolling window -------------
// grid (DIN/256, Lq/64, 16): z = b + 8*dir. fp16 in, fp16 out (coalesced half stores).
__global__ __launch_bounds__(256)
void conv_kernel(const float* __restrict__ w1, const float* __restrict__ b1,
                 const float* __restrict__ w2, const float* __restrict__ b2)
{
    int d   = blockIdx.x*256 + threadIdx.x;
    int b   = blockIdx.z & 7;
    int dir = blockIdx.z >> 3;
    int T0  = blockIdx.y * 64;

    const h16* xz   = dir ? g_xz2h : g_xz1h;
    const float* w  = dir ? w2 : w1;
    const float* cb = dir ? b2 : b1;
    h16* xch        = dir ? g_xc2h : g_xc1h;

    const float4 wv = *reinterpret_cast<const float4*>(w + d*4);
    const float bias = cb[d];
    const h16* X = xz + ((size_t)b*Lq)*(2*DIN) + d;
    const size_t rs = 2*DIN;

    if (dir == 0) {
        float v0 = (T0-1 >= 0) ? __half2float(X[(size_t)(T0-1)*rs]) : 0.f;
        float v1 = (T0-2 >= 0) ? __half2float(X[(size_t)(T0-2)*rs]) : 0.f;
        float v2 = (T0-3 >= 0) ? __half2float(X[(size_t)(T0-3)*rs]) : 0.f;
#pragma unroll 4
        for (int t = T0; t < T0+64; t++) {
            float vn = __half2float(X[(size_t)t*rs]);
            float s = bias + wv.w*vn + wv.z*v0 + wv.y*v1 + wv.x*v2;
            v2 = v1; v1 = v0; v0 = vn;
            float r = s / (1.f + __expf(-s));
            xch[((size_t)b*Lq + t)*DIN + d] = __float2half_rn(r);
        }
    } else {
        float v0 = __half2float(X[(size_t)T0*rs]);
        float v1 = (T0+1 < Lq) ? __half2float(X[(size_t)(T0+1)*rs]) : 0.f;
        float v2 = (T0+2 < Lq) ? __half2float(X[(size_t)(T0+2)*rs]) : 0.f;
#pragma unroll 4
        for (int t = T0; t < T0+64; t++) {
            float vn = (t+3 < Lq) ? __half2float(X[(size_t)(t+3)*rs]) : 0.f;
            float s = bias + wv.w*v0 + wv.z*v1 + wv.y*v2 + wv.x*vn;
            v0 = v1; v1 = v2; v2 = vn;
            float r = s / (1.f + __expf(-s));
            xch[((size_t)b*Lq + t)*DIN + d] = __float2half_rn(r);
        }
    }
}

// ---------------- dt = softplus(xdbl[:, :32] @ W^T + b), tiled smem GEMM -> fp16 --------
__global__ __launch_bounds__(256)
void dtg_kernel(const float* __restrict__ w1, const float* __restrict__ w2,
                const float* __restrict__ b1, const float* __restrict__ b2)
{
    int dir = blockIdx.z;
    const float* xdbl = dir ? g_xdbl2 : g_xdbl1;
    const float* W    = dir ? w2 : w1;
    const float* bias = dir ? b2 : b1;
    h16* outp         = dir ? g_dt2h : g_dt1h;

    __shared__ float sX[128][33];
    __shared__ float sW[128][33];

    const int tid = threadIdx.x;
    const int d0 = blockIdx.x*128, r0 = blockIdx.y*128;

#pragma unroll
    for (int i = 0; i < 16; i++) {
        int idx = tid + i*256;
        int r = idx >> 5, k = idx & 31;
        sX[r][k] = xdbl[(size_t)(r0+r)*64 + k];
    }
#pragma unroll
    for (int i = 0; i < 16; i++) {
        int idx = tid + i*256;
        int dd = idx >> 5, k = idx & 31;
        sW[dd][k] = W[(size_t)(d0+dd)*DTR + k];
    }
    __syncthreads();

    const int tx = tid & 15, ty = tid >> 4;
    float acc[8][8];
#pragma unroll
    for (int i = 0; i < 8; i++)
#pragma unroll
        for (int j = 0; j < 8; j++) acc[i][j] = 0.f;

#pragma unroll
    for (int k = 0; k < 32; k++) {
        float a[8], bb[8];
#pragma unroll
        for (int i = 0; i < 8; i++) a[i] = sX[ty + i*16][k];
#pragma unroll
        for (int j = 0; j < 8; j++) bb[j] = sW[tx + j*16][k];
#pragma unroll
        for (int i = 0; i < 8; i++)
#pragma unroll
            for (int j = 0; j < 8; j++) acc[i][j] = fmaf(a[i], bb[j], acc[i][j]);
    }

#pragma unroll
    for (int i = 0; i < 8; i++) {
#pragma unroll
        for (int j = 0; j < 8; j++) {
            int r = r0 + ty + i*16, c = d0 + tx + j*16;
            float s = acc[i][j] + bias[c];
            float sp = (s > 20.f) ? s : log1pf(__expf(s));
            outp[(size_t)r*DIN + c] = __float2half_rn(sp);
        }
    }
}

// ---------------- selective scan (R6 structure + ex2, fp16 dt/u/z) ----------------------
// grid (1024, 2), 64 threads. 2 states/lane, 4 ch/warp, prefetch.
__global__ __launch_bounds__(64)
void scan_kernel(const float* __restrict__ D1, const float* __restrict__ D2)
{
    int dir = blockIdx.y;
    const h16*   dth  = dir ? g_dt2h : g_dt1h;
    const h16*   xch  = dir ? g_xc2h : g_xc1h;
    const float* xdbl = dir ? g_xdbl2: g_xdbl1;
    const h16*   xzh  = dir ? g_xz2h : g_xz1h;
    const float* Aexp = g_A + dir*DIN*DS;
    const float* Dv_  = dir ? D2 : D1;

    int warp = threadIdx.x >> 5, lane = threadIdx.x & 31;
    int sl  = lane & 7;                      // state lane (2 states each)
    int chl = lane >> 3;                     // channel within warp
    int c   = blockIdx.x*8 + warp*4 + chl;   // channels per dir: 8192
    int b   = c >> 10, d = c & (DIN-1);

    const float2 a2 = *(const float2*)(Aexp + d*DS + sl*2);
    const float Dd = Dv_[d];
    float hx = 0.f, hy = 0.f;
    const int rbase = b*Lq;
    const int step = dir ? -1 : 1;

    int t = dir ? (Lq-1) : 0;
    size_t row = rbase + t;
    float dtv = __half2float(dth[row*DIN + d]);
    float uv  = __half2float(xch[row*DIN + d]);
    float2 Bv = *(const float2*)(xdbl + row*64 + DTR + sl*2);
    float2 Cv = *(const float2*)(xdbl + row*64 + DTR + DS + sl*2);
    float zv  = __half2float(xzh[row*(2*DIN) + DIN + d]);

    for (int i = 0; i < Lq; i++) {
        int tn = t + step;
        if (tn < 0) tn = 0; if (tn > Lq-1) tn = Lq-1;
        size_t rown = rbase + tn;
        // prefetch next
        float dtn = __half2float(dth[rown*DIN + d]);
        float un  = __half2float(xch[rown*DIN + d]);
        float2 Bn = *(const float2*)(xdbl + rown*64 + DTR + sl*2);
        float2 Cn = *(const float2*)(xdbl + rown*64 + DTR + DS + sl*2);
        float zn  = __half2float(xzh[rown*(2*DIN) + DIN + d]);
        // compute current
        float du = dtv*uv;
        hx = fmaf(ex2(dtv*a2.x), hx, du*Bv.x);
        hy = fmaf(ex2(dtv*a2.y), hy, du*Bv.y);
        float p = hx*Cv.x + hy*Cv.y;
        p += __shfl_xor_sync(0xffffffffu, p, 1);
        p += __shfl_xor_sync(0xffffffffu, p, 2);
        p += __shfl_xor_sync(0xffffffffu, p, 4);
        if (sl == 0) {
            float yv = (p + uv*Dd) * (zv / (1.f + __expf(-zv)));
            g_yh[row*(2*DIN) + dir*DIN + d] = __float2half_rn(yv);
        }
        dtv = dtn; uv = un; Bv = Bn; Cv = Cn; zv = zn;
        t = tn; row = rown;
    }
}

// ---------------- LayerNorm: out = LN(a + b) * g + beta (+ optional fp16 copy) ---------
__global__ __launch_bounds__(256)
void ln_kernel(const float* __restrict__ a, const float* __restrict__ b,
               const float* __restrict__ g, const float* __restrict__ beta,
               float* __restrict__ out, h16* __restrict__ oh)
{
    int row  = blockIdx.x*8 + (threadIdx.x >> 5);
    int lane = threadIdx.x & 31;
    const float* pa = a + (size_t)row*DM;
    const float* pb = b + (size_t)row*DM;
    float v[16];
    float s = 0.f, s2 = 0.f;
#pragma unroll
    for (int i = 0; i < 16; i++) {
        int cix = lane + i*32;
        float x = pa[cix] + pb[cix];
        v[i] = x; s += x; s2 = fmaf(x, x, s2);
    }
#pragma unroll
    for (int off = 16; off > 0; off >>= 1) {
        s  += __shfl_xor_sync(0xffffffffu, s,  off);
        s2 += __shfl_xor_sync(0xffffffffu, s2, off);
    }
    float mean = s * (1.f/DM);
    float var  = s2 * (1.f/DM) - mean*mean;
    float inv  = rsqrtf(var + 1e-5f);
    float* po = out + (size_t)row*DM;
#pragma unroll
    for (int i = 0; i < 16; i++) {
        int cix = lane + i*32;
        float r = (v[i]-mean)*inv*g[cix] + beta[cix];
        po[cix] = r;
        if (oh) oh[(size_t)row*DM + cix] = __float2half_rn(r);
    }
}

// ---------------- launch ----------------
extern "C" void kernel_launch(void* const* d_in, const int* in_sizes, int n_in,
                              void* d_out, int out_size)
{
    const float* x       = (const float*)d_in[0];
    const float* in1_w   = (const float*)d_in[1];
    const float* conv1_w = (const float*)d_in[2];
    const float* conv1_b = (const float*)d_in[3];
    const float* xp1_w   = (const float*)d_in[4];
    const float* dtp1_w  = (const float*)d_in[5];
    const float* dtp1_b  = (const float*)d_in[6];
    const float* Alog1   = (const float*)d_in[7];
    const float* D1      = (const float*)d_in[8];
    const float* outp1_w = (const float*)d_in[9];
    const float* in2_w   = (const float*)d_in[10];
    const float* conv2_w = (const float*)d_in[11];
    const float* conv2_b = (const float*)d_in[12];
    const float* xp2_w   = (const float*)d_in[13];
    const float* dtp2_w  = (const float*)d_in[14];
    const float* dtp2_b  = (const float*)d_in[15];
    const float* Alog2   = (const float*)d_in[16];
    const float* D2      = (const float*)d_in[17];
    const float* outp2_w = (const float*)d_in[18];
    const float* c1_w    = (const float*)d_in[19];
    const float* c1_b    = (const float*)d_in[20];
    const float* c2_w    = (const float*)d_in[21];
    const float* c2_b    = (const float*)d_in[22];
    const float* ln1_g   = (const float*)d_in[23];
    const float* ln1_b   = (const float*)d_in[24];
    const float* ln2_g   = (const float*)d_in[25];
    const float* ln2_b   = (const float*)d_in[26];
    float* out = (float*)d_out;

    float *xdbl1,*xdbl2,*o,*xln,*yff;
    cudaGetSymbolAddress((void**)&xdbl1,g_xdbl1);
    cudaGetSymbolAddress((void**)&xdbl2,g_xdbl2);
    cudaGetSymbolAddress((void**)&o,    g_o);
    cudaGetSymbolAddress((void**)&xln,  g_xln);
    cudaGetSymbolAddress((void**)&yff,  g_yff);

    h16 *xz1h,*xz2h,*xh,*xc1h,*xc2h,*yh,*xlnh,*hffh;
    cudaGetSymbolAddress((void**)&xz1h,g_xz1h);
    cudaGetSymbolAddress((void**)&xz2h,g_xz2h);
    cudaGetSymbolAddress((void**)&xh,  g_xh);
    cudaGetSymbolAddress((void**)&xc1h,g_xc1h);
    cudaGetSymbolAddress((void**)&xc2h,g_xc2h);
    cudaGetSymbolAddress((void**)&yh,  g_yh);
    cudaGetSymbolAddress((void**)&xlnh,g_xlnh);
    cudaGetSymbolAddress((void**)&hffh,g_hffh);

    h16 *win1h,*win2h,*wxp1h,*wxp2h,*woh,*wc1h,*wc2h;
    cudaGetSymbolAddress((void**)&win1h,g_win1h);
    cudaGetSymbolAddress((void**)&win2h,g_win2h);
    cudaGetSymbolAddress((void**)&wxp1h,g_wxp1h);
    cudaGetSymbolAddress((void**)&wxp2h,g_wxp2h);
    cudaGetSymbolAddress((void**)&woh,  g_woh);
    cudaGetSymbolAddress((void**)&wc1h, g_wc1h);
    cudaGetSymbolAddress((void**)&wc2h, g_wc2h);

    // dyn smem: 3 stages x (A 10240 + B BN*80); EPI=6 staging needs 128*(BN+8)*2 <= this
    const int SM128 = 3*(10240 + 10240);  // 61440
    const int SM64  = 3*(10240 + 5120);   // 46080
    cudaFuncSetAttribute(tgemm<128,6>, cudaFuncAttributeMaxDynamicSharedMemorySize, SM128);
    cudaFuncSetAttribute(tgemm<128,0>, cudaFuncAttributeMaxDynamicSharedMemorySize, SM128);
    cudaFuncSetAttribute(tgemm<128,3>, cudaFuncAttributeMaxDynamicSharedMemorySize, SM128);
    cudaFuncSetAttribute(tgemm<128,4>, cudaFuncAttributeMaxDynamicSharedMemorySize, SM128);
    cudaFuncSetAttribute(tgemm<64,0>,  cudaFuncAttributeMaxDynamicSharedMemorySize, SM64);

    prep_kernel<<<64,256>>>(Alog1, Alog2);
    convert_all<<<(CV_TOTAL+255)/256,256>>>(x, in1_w, in2_w, xp1_w, xp2_w,
                                            outp1_w, outp2_w, c1_w, c2_w);

    // in_proj, both dirs: (8192x2048) = x @ W^T, K=512 -> fp16 xz (smem-staged stores)
    {
        dim3 g(2*DIN/128, MROWS/128, 2);
        GArg a0 = {xh, win1h, nullptr, xz1h};
        GArg a1 = {xh, win2h, nullptr, xz2h};
        tgemm<128,6><<<g,256,SM128>>>(a0, a1, DM, DM, 2*DIN, DM, nullptr, nullptr);
    }

    // depthwise conv + silu (rolling window, fp16 in, fp16 out)
    {
        dim3 g(DIN/256, Lq/64, 16);
        conv_kernel<<<g,256>>>(conv1_w, conv1_b, conv2_w, conv2_b);
    }

    // x_proj, both dirs: (8192x64) = xc @ xp_w^T, K=1024
    {
        dim3 g(1, MROWS/128, 2);
        GArg a0 = {xc1h, wxp1h, xdbl1, nullptr};
        GArg a1 = {xc2h, wxp2h, xdbl2, nullptr};
        tgemm<64,0><<<g,128,SM64>>>(a0, a1, DIN, DIN, 64, DIN, nullptr, nullptr);
    }

    // dt_proj + softplus (tiled) -> fp16 dt
    {
        dim3 g(DIN/128, MROWS/128, 2);
        dtg_kernel<<<g,256>>>(dtp1_w, dtp2_w, dtp1_b, dtp2_b);
    }

    // selective scan + gate -> fp16 y
    {
        dim3 gs(1024, 2);
        scan_kernel<<<gs,64>>>(D1, D2);
    }

    // out_proj fused: o = [y1|y2](8192x2048) @ fused_w^T, K=2048
    {
        dim3 g(DM/128, MROWS/128, 1);
        GArg a0 = {yh, woh, o, nullptr};
        tgemm<128,0><<<g,256,SM128>>>(a0, a0, 2*DIN, 2*DIN, DM, 2*DIN, nullptr, nullptr);
    }

    // LN1: xln = LN(o + x)  (+ fp16 copy)
    ln_kernel<<<MROWS/8,256>>>(o, x, ln1_g, ln1_b, xln, xlnh);

    // FFN
    {
        dim3 g1(DFF/128, MROWS/128, 1);
        GArg a0 = {xlnh, wc1h, nullptr, hffh};
        tgemm<128,4><<<g1,256,SM128>>>(a0, a0, DM, DM, DFF, DM, c1_b, c1_b);
        dim3 g2(DM/128, MROWS/128, 1);
        GArg a2 = {hffh, wc2h, yff, nullptr};
        tgemm<128,3><<<g2,256,SM128>>>(a2, a2, DFF, DFF, DM, DFF, c2_b, c2_b);
    }

    // LN2: out = LN(xln + yff)
    ln_kernel<<<MROWS/8,256>>>(xln, yff, ln2_g, ln2_b, out, nullptr);
}

// round 14
// speedup vs baseline: 1.0622x; 1.0622x over previous
#include <cuda_runtime.h>
#include <cuda_fp16.h>
#include <math.h>
#include <stdint.h>

#define Bq   8
#define Lq   1024
#define DM   512
#define DIN  1024
#define DFF  2048
#define DS   16
#define DTR  32
#define MROWS (Bq*Lq)   /* 8192 token rows */

typedef __half h16;

// ---------------- fp32 scratch ----------------
__device__ float g_xz1 [MROWS*2*DIN];
__device__ float g_xz2 [MROWS*2*DIN];
__device__ float g_xdbl1[MROWS*64];
__device__ float g_xdbl2[MROWS*64];
__device__ float g_o   [MROWS*DM];
__device__ float g_xln [MROWS*DM];
__device__ float g_yff [MROWS*DM];
__device__ float g_A   [2*DIN*DS];     // -exp(Alog) * log2(e)

// ---------------- fp16 activations ----------------
__device__ h16 g_xh  [MROWS*DM];
__device__ h16 g_xc1h[MROWS*DIN];
__device__ h16 g_xc2h[MROWS*DIN];
__device__ h16 g_dt1h[MROWS*DIN];
__device__ h16 g_dt2h[MROWS*DIN];
__device__ h16 g_yh  [MROWS*2*DIN];    // [dir0 | dir1] per row
__device__ h16 g_xlnh[MROWS*DM];
__device__ h16 g_hffh[MROWS*DFF];

// ---------------- fp16 weights ----------------
__device__ h16 g_win1h[2*DIN*DM];
__device__ h16 g_win2h[2*DIN*DM];
__device__ h16 g_wxp1h[64*DIN];
__device__ h16 g_wxp2h[64*DIN];
__device__ h16 g_woh  [DM*2*DIN];      // fused [out1 | out2]
__device__ h16 g_wc1h [DFF*DM];
__device__ h16 g_wc2h [DM*DFF];

// ======================= helpers =======================
__device__ __forceinline__ float ex2(float x) {
    float r;
    asm("ex2.approx.f32 %0, %1;" : "=f"(r) : "f"(x));
    return r;
}
__device__ __forceinline__ uint32_t smem_u32(const void* p) {
    uint32_t a;
    asm("{ .reg .u64 t; cvta.to.shared.u64 t, %1; cvt.u32.u64 %0, t; }" : "=r"(a) : "l"(p));
    return a;
}
__device__ __forceinline__ void ldmx4(uint32_t* r, uint32_t addr) {
    asm volatile("ldmatrix.sync.aligned.m8n8.x4.shared.b16 {%0,%1,%2,%3}, [%4];"
                 : "=r"(r[0]), "=r"(r[1]), "=r"(r[2]), "=r"(r[3]) : "r"(addr));
}
__device__ __forceinline__ void ldmx2(uint32_t* r, uint32_t addr) {
    asm volatile("ldmatrix.sync.aligned.m8n8.x2.shared.b16 {%0,%1}, [%2];"
                 : "=r"(r[0]), "=r"(r[1]) : "r"(addr));
}
__device__ __forceinline__ void hmma(float* d, const uint32_t* a, const uint32_t* b) {
    asm volatile(
        "mma.sync.aligned.m16n8k16.row.col.f32.f16.f16.f32 "
        "{%0,%1,%2,%3}, {%4,%5,%6,%7}, {%8,%9}, {%0,%1,%2,%3};"
        : "+f"(d[0]), "+f"(d[1]), "+f"(d[2]), "+f"(d[3])
        : "r"(a[0]), "r"(a[1]), "r"(a[2]), "r"(a[3]), "r"(b[0]), "r"(b[1]));
}
__device__ __forceinline__ void cpa16(uint32_t dst, const void* src) {
    asm volatile("cp.async.cg.shared.global [%0], [%1], 16;" :: "r"(dst), "l"(src));
}
#define CP_COMMIT() asm volatile("cp.async.commit_group;" ::: "memory")
template<int N> __device__ __forceinline__ void cp_wait() {
    asm volatile("cp.async.wait_group %0;" :: "n"(N) : "memory");
}
__device__ __forceinline__ float gelu_exact(float x) {
    return 0.5f * x * (1.0f + erff(x * 0.70710678118654752f));
}

struct GArg { const h16* A; const h16* B; float* C; h16* Ch; };

// ======================= fp16 HMMA GEMM, 4-stage cp.async =======================
// C[m,n] = sum_k A[m,k]*B[n,k]; fp16 in, fp32 accum. blockIdx.z selects arg set.
// Block tile 128 x BN, BK=32, warp tile 64x32.
// EPI: 0 = fp32 store, 3 = bias fp32, 4 = bias+GELU fp16 store.
template<int BN, int EPI>
__global__ __launch_bounds__(64*(BN/32))
void tgemm(GArg g0, GArg g1, int lda, int ldb, int ldc, int K,
           const float* bias0, const float* bias1)
{
    constexpr int WN = BN / 32;
    constexpr int T  = 64 * WN;
    constexpr int PK = 40;                    // padded k stride (elems), 80B
    constexpr int ASZ = 128 * PK * 2;         // bytes
    constexpr int BSZ = BN  * PK * 2;
    constexpr int STG = ASZ + BSZ;

    const GArg ga = blockIdx.z ? g1 : g0;
    const float* bias = blockIdx.z ? bias1 : bias0;

    extern __shared__ char smem[];
    const uint32_t base = smem_u32(smem);

    const int tid  = threadIdx.x;
    const int wid  = tid >> 5, lane = tid & 31;
    const int warp_m = wid & 1, warp_n = wid >> 1;
    const int m0 = blockIdx.y * 128;
    const int n0 = blockIdx.x * BN;

    float acc[4][4][4];
#pragma unroll
    for (int i = 0; i < 4; i++)
#pragma unroll
        for (int j = 0; j < 4; j++)
#pragma unroll
            for (int q = 0; q < 4; q++) acc[i][j][q] = 0.f;

    const int rA = (lane & 15);
    const int cA = (lane >> 4) * 8;
    const int l2 = lane & 15;
    const int rB = l2 & 7;
    const int cB = (l2 >> 3) * 8;

    auto load_tiles = [&](int k0, uint32_t aS, uint32_t bS) {
#pragma unroll
        for (int m = 0; m < 512 / T; m++) {
            int cid = tid + m * T;
            int row = cid >> 2, c4 = cid & 3;
            cpa16(aS + (row * PK + c4 * 8) * 2,
                  ga.A + (size_t)(m0 + row) * lda + k0 + c4 * 8);
        }
#pragma unroll
        for (int m = 0; m < (BN * 4) / T; m++) {
            int cid = tid + m * T;
            int row = cid >> 2, c4 = cid & 3;
            cpa16(bS + (row * PK + c4 * 8) * 2,
                  ga.B + (size_t)(n0 + row) * ldb + k0 + c4 * 8);
        }
    };

    const int nk = K / 32;
    // preload 3 stages (nk >= 4 for all our GEMMs: min K=512)
    load_tiles(0, base, base + ASZ);
    CP_COMMIT();
    load_tiles(32, base + STG, base + STG + ASZ);
    CP_COMMIT();
    load_tiles(64, base + 2*STG, base + 2*STG + ASZ);
    CP_COMMIT();

    for (int i = 0; i < nk; i++) {
        if (i + 2 < nk)      cp_wait<2>();
        else if (i + 1 < nk) cp_wait<1>();
        else                 cp_wait<0>();
        __syncthreads();
        if (i + 3 < nk) {
            int s = (i + 3) & 3;
            load_tiles((i + 3) * 32, base + s * STG, base + s * STG + ASZ);
            CP_COMMIT();
        }
        const uint32_t aS = base + (i & 3) * STG;
        const uint32_t bS = aS + ASZ;

#pragma unroll
        for (int kk = 0; kk < 32; kk += 16) {
            uint32_t Ar[4][4], Br[4][2];
            const int aoff = kk + cA;
            const int boff = kk + cB;
#pragma unroll
            for (int mf = 0; mf < 4; mf++)
                ldmx4(Ar[mf], aS + ((warp_m*64 + mf*16 + rA) * PK + aoff) * 2);
#pragma unroll
            for (int nf = 0; nf < 4; nf++)
                ldmx2(Br[nf], bS + ((warp_n*32 + nf*8 + rB) * PK + boff) * 2);
#pragma unroll
            for (int mf = 0; mf < 4; mf++)
#pragma unroll
                for (int nf = 0; nf < 4; nf++)
                    hmma(acc[mf][nf], Ar[mf], Br[nf]);
        }
    }

    // ---- epilogue ----
    const int rr = lane >> 2;
    const int cc = (lane & 3) * 2;
#pragma unroll
    for (int mf = 0; mf < 4; mf++) {
#pragma unroll
        for (int nf = 0; nf < 4; nf++) {
            int col = n0 + warp_n*32 + nf*8 + cc;
            float b0 = 0.f, b1 = 0.f;
            if (EPI == 3 || EPI == 4) { b0 = bias[col]; b1 = bias[col+1]; }
#pragma unroll
            for (int h = 0; h < 2; h++) {
                int row = m0 + warp_m*64 + mf*16 + rr + h*8;
                float v0 = acc[mf][nf][h*2+0];
                float v1 = acc[mf][nf][h*2+1];
                if (EPI == 3) {
                    *reinterpret_cast<float2*>(ga.C + (size_t)row * ldc + col) =
                        make_float2(v0 + b0, v1 + b1);
                } else if (EPI == 4) {
                    v0 = gelu_exact(v0 + b0); v1 = gelu_exact(v1 + b1);
                    *reinterpret_cast<__half2*>(ga.Ch + (size_t)row * ldc + col) =
                        __floats2half2_rn(v0, v1);
                } else {
                    *reinterpret_cast<float2*>(ga.C + (size_t)row * ldc + col) =
                        make_float2(v0, v1);
                }
            }
        }
    }
}

// ---------------- single launch: all fp32->fp16 conversions + A prep ----------------
#define SZ_X   (MROWS*DM)
#define SZ_IN  (2*DIN*DM)
#define SZ_XP  (64*DIN)
#define SZ_OP  (DM*DIN)
#define SZ_C1  (DFF*DM)
#define SZ_C2  (DM*DFF)
#define SZ_A   (DIN*DS)
#define CV_TOTAL (SZ_X + 2*SZ_IN + 2*SZ_XP + 2*SZ_OP + SZ_C1 + SZ_C2 + 2*SZ_A)

__global__ void convert_all(const float* __restrict__ x,
                            const float* __restrict__ in1, const float* __restrict__ in2,
                            const float* __restrict__ xp1, const float* __restrict__ xp2,
                            const float* __restrict__ op1, const float* __restrict__ op2,
                            const float* __restrict__ c1,  const float* __restrict__ c2,
                            const float* __restrict__ Alog1, const float* __restrict__ Alog2)
{
    long j = (long)blockIdx.x*256 + threadIdx.x;
    if (j < SZ_X)  { g_xh[j] = __float2half_rn(x[j]); return; }    j -= SZ_X;
    if (j < SZ_IN) { g_win1h[j] = __float2half_rn(in1[j]); return; } j -= SZ_IN;
    if (j < SZ_IN) { g_win2h[j] = __float2half_rn(in2[j]); return; } j -= SZ_IN;
    if (j < SZ_XP) { g_wxp1h[j] = __float2half_rn(xp1[j]); return; } j -= SZ_XP;
    if (j < SZ_XP) { g_wxp2h[j] = __float2half_rn(xp2[j]); return; } j -= SZ_XP;
    if (j < SZ_OP) { long r = j/DIN, k = j%DIN;
                     g_woh[r*2*DIN + k] = __float2half_rn(op1[j]); return; } j -= SZ_OP;
    if (j < SZ_OP) { long r = j/DIN, k = j%DIN;
                     g_woh[r*2*DIN + DIN + k] = __float2half_rn(op2[j]); return; } j -= SZ_OP;
    if (j < SZ_C1) { g_wc1h[j] = __float2half_rn(c1[j]); return; } j -= SZ_C1;
    if (j < SZ_C2) { g_wc2h[j] = __float2half_rn(c2[j]); return; } j -= SZ_C2;
    if (j < SZ_A)  { g_A[j] = -__expf(Alog1[j]) * 1.44269504088896f; return; } j -= SZ_A;
    if (j < SZ_A)  { g_A[SZ_A + j] = -__expf(Alog2[j]) * 1.44269504088896f; }
}

// ---------------- depthwise causal conv (k=4) + bias + SiLU, rolling window -------------
// grid (DIN/256, Lq/64, 16): z = b + 8*dir. fp32 in, fp16 out (coalesced half stores).
__global__ __launch_bounds__(256)
void conv_kernel(const float* __restrict__ w1, const float* __restrict__ b1,
                 const float* __restrict__ w2, const float* __restrict__ b2)
{
    int d   = blockIdx.x*256 + threadIdx.x;
    int b   = blockIdx.z & 7;
    int dir = blockIdx.z >> 3;
    int T0  = blockIdx.y * 64;

    const float* xz = dir ? g_xz2 : g_xz1;
    const float* w  = dir ? w2 : w1;
    const float* cb = dir ? b2 : b1;
    h16* xch        = dir ? g_xc2h : g_xc1h;

    const float4 wv = *reinterpret_cast<const float4*>(w + d*4);
    const float bias = cb[d];
    const float* X = xz + ((size_t)b*Lq)*(2*DIN) + d;
    const size_t rs = 2*DIN;

    if (dir == 0) {
        float v0 = (T0-1 >= 0) ? X[(size_t)(T0-1)*rs] : 0.f;
        float v1 = (T0-2 >= 0) ? X[(size_t)(T0-2)*rs] : 0.f;
        float v2 = (T0-3 >= 0) ? X[(size_t)(T0-3)*rs] : 0.f;
#pragma unroll 4
        for (int t = T0; t < T0+64; t++) {
            float vn = X[(size_t)t*rs];
            float s = bias + wv.w*vn + wv.z*v0 + wv.y*v1 + wv.x*v2;
            v2 = v1; v1 = v0; v0 = vn;
            float r = s / (1.f + __expf(-s));
            xch[((size_t)b*Lq + t)*DIN + d] = __float2half_rn(r);
        }
    } else {
        float v0 = X[(size_t)T0*rs];
        float v1 = (T0+1 < Lq) ? X[(size_t)(T0+1)*rs] : 0.f;
        float v2 = (T0+2 < Lq) ? X[(size_t)(T0+2)*rs] : 0.f;
#pragma unroll 4
        for (int t = T0; t < T0+64; t++) {
            float vn = (t+3 < Lq) ? X[(size_t)(t+3)*rs] : 0.f;
            float s = bias + wv.w*v0 + wv.z*v1 + wv.y*v2 + wv.x*vn;
            v0 = v1; v1 = v2; v2 = vn;
            float r = s / (1.f + __expf(-s));
            xch[((size_t)b*Lq + t)*DIN + d] = __float2half_rn(r);
        }
    }
}

// ---------------- dt = softplus(xdbl[:, :32] @ W^T + b), tiled smem GEMM -> fp16 --------
__global__ __launch_bounds__(256)
void dtg_kernel(const float* __restrict__ w1, const float* __restrict__ w2,
                const float* __restrict__ b1, const float* __restrict__ b2)
{
    int dir = blockIdx.z;
    const float* xdbl = dir ? g_xdbl2 : g_xdbl1;
    const float* W    = dir ? w2 : w1;
    const float* bias = dir ? b2 : b1;
    h16* outp         = dir ? g_dt2h : g_dt1h;

    __shared__ float sX[128][33];
    __shared__ float sW[128][33];

    const int tid = threadIdx.x;
    const int d0 = blockIdx.x*128, r0 = blockIdx.y*128;

#pragma unroll
    for (int i = 0; i < 16; i++) {
        int idx = tid + i*256;
        int r = idx >> 5, k = idx & 31;
        sX[r][k] = xdbl[(size_t)(r0+r)*64 + k];
    }
#pragma unroll
    for (int i = 0; i < 16; i++) {
        int idx = tid + i*256;
        int dd = idx >> 5, k = idx & 31;
        sW[dd][k] = W[(size_t)(d0+dd)*DTR + k];
    }
    __syncthreads();

    const int tx = tid & 15, ty = tid >> 4;
    float acc[8][8];
#pragma unroll
    for (int i = 0; i < 8; i++)
#pragma unroll
        for (int j = 0; j < 8; j++) acc[i][j] = 0.f;

#pragma unroll
    for (int k = 0; k < 32; k++) {
        float a[8], bb[8];
#pragma unroll
        for (int i = 0; i < 8; i++) a[i] = sX[ty + i*16][k];
#pragma unroll
        for (int j = 0; j < 8; j++) bb[j] = sW[tx + j*16][k];
#pragma unroll
        for (int i = 0; i < 8; i++)
#pragma unroll
            for (int j = 0; j < 8; j++) acc[i][j] = fmaf(a[i], bb[j], acc[i][j]);
    }

#pragma unroll
    for (int i = 0; i < 8; i++) {
#pragma unroll
        for (int j = 0; j < 8; j++) {
            int r = r0 + ty + i*16, c = d0 + tx + j*16;
            float s = acc[i][j] + bias[c];
            float sp = (s > 20.f) ? s : log1pf(__expf(s));
            outp[(size_t)r*DIN + c] = __float2half_rn(sp);
        }
    }
}

// ---------------- selective scan (R6 structure + ex2, fp16 dt/u): ----------------------
// grid (1024, 2), 64 threads. 2 states/lane, 4 ch/warp, prefetch.
__global__ __launch_bounds__(64)
void scan_kernel(const float* __restrict__ D1, const float* __restrict__ D2)
{
    int dir = blockIdx.y;
    const h16*   dth  = dir ? g_dt2h : g_dt1h;
    const h16*   xch  = dir ? g_xc2h : g_xc1h;
    const float* xdbl = dir ? g_xdbl2: g_xdbl1;
    const float* xz   = dir ? g_xz2  : g_xz1;
    const float* Aexp = g_A + dir*DIN*DS;
    const float* Dv_  = dir ? D2 : D1;

    int warp = threadIdx.x >> 5, lane = threadIdx.x & 31;
    int sl  = lane & 7;                      // state lane (2 states each)
    int chl = lane >> 3;                     // channel within warp
    int c   = blockIdx.x*8 + warp*4 + chl;   // channels per dir: 8192
    int b   = c >> 10, d = c & (DIN-1);

    const float2 a2 = *(const float2*)(Aexp + d*DS + sl*2);
    const float Dd = Dv_[d];
    float hx = 0.f, hy = 0.f;
    const int rbase = b*Lq;
    const int step = dir ? -1 : 1;

    int t = dir ? (Lq-1) : 0;
    size_t row = rbase + t;
    float dtv = __half2float(dth[row*DIN + d]);
    float uv  = __half2float(xch[row*DIN + d]);
    float2 Bv = *(const float2*)(xdbl + row*64 + DTR + sl*2);
    float2 Cv = *(const float2*)(xdbl + row*64 + DTR + DS + sl*2);
    float zv  = xz[row*(2*DIN) + DIN + d];

    for (int i = 0; i < Lq; i++) {
        int tn = t + step;
        if (tn < 0) tn = 0; if (tn > Lq-1) tn = Lq-1;
        size_t rown = rbase + tn;
        // prefetch next
        float dtn = __half2float(dth[rown*DIN + d]);
        float un  = __half2float(xch[rown*DIN + d]);
        float2 Bn = *(const float2*)(xdbl + rown*64 + DTR + sl*2);
        float2 Cn = *(const float2*)(xdbl + rown*64 + DTR + DS + sl*2);
        float zn  = xz[rown*(2*DIN) + DIN + d];
        // compute current
        float du = dtv*uv;
        hx = fmaf(ex2(dtv*a2.x), hx, du*Bv.x);
        hy = fmaf(ex2(dtv*a2.y), hy, du*Bv.y);
        float p = hx*Cv.x + hy*Cv.y;
        p += __shfl_xor_sync(0xffffffffu, p, 1);
        p += __shfl_xor_sync(0xffffffffu, p, 2);
        p += __shfl_xor_sync(0xffffffffu, p, 4);
        if (sl == 0) {
            float yv = (p + uv*Dd) * (zv / (1.f + __expf(-zv)));
            g_yh[row*(2*DIN) + dir*DIN + d] = __float2half_rn(yv);
        }
        dtv = dtn; uv = un; Bv = Bn; Cv = Cn; zv = zn;
        t = tn; row = rown;
    }
}

// ---------------- LayerNorm: out = LN(a + b) * g + beta (+ optional fp16 copy) ---------
__global__ __launch_bounds__(256)
void ln_kernel(const float* __restrict__ a, const float* __restrict__ b,
               const float* __restrict__ g, const float* __restrict__ beta,
               float* __restrict__ out, h16* __restrict__ oh)
{
    int row  = blockIdx.x*8 + (threadIdx.x >> 5);
    int lane = threadIdx.x & 31;
    const float* pa = a + (size_t)row*DM;
    const float* pb = b + (size_t)row*DM;
    float v[16];
    float s = 0.f, s2 = 0.f;
#pragma unroll
    for (int i = 0; i < 16; i++) {
        int cix = lane + i*32;
        float x = pa[cix] + pb[cix];
        v[i] = x; s += x; s2 = fmaf(x, x, s2);
    }
#pragma unroll
    for (int off = 16; off > 0; off >>= 1) {
        s  += __shfl_xor_sync(0xffffffffu, s,  off);
        s2 += __shfl_xor_sync(0xffffffffu, s2, off);
    }
    float mean = s * (1.f/DM);
    float var  = s2 * (1.f/DM) - mean*mean;
    float inv  = rsqrtf(var + 1e-5f);
    float* po = out + (size_t)row*DM;
#pragma unroll
    for (int i = 0; i < 16; i++) {
        int cix = lane + i*32;
        float r = (v[i]-mean)*inv*g[cix] + beta[cix];
        po[cix] = r;
        if (oh) oh[(size_t)row*DM + cix] = __float2half_rn(r);
    }
}

// ---------------- launch ----------------
extern "C" void kernel_launch(void* const* d_in, const int* in_sizes, int n_in,
                              void* d_out, int out_size)
{
    const float* x       = (const float*)d_in[0];
    const float* in1_w   = (const float*)d_in[1];
    const float* conv1_w = (const float*)d_in[2];
    const float* conv1_b = (const float*)d_in[3];
    const float* xp1_w   = (const float*)d_in[4];
    const float* dtp1_w  = (const float*)d_in[5];
    const float* dtp1_b  = (const float*)d_in[6];
    const float* Alog1   = (const float*)d_in[7];
    const float* D1      = (const float*)d_in[8];
    const float* outp1_w = (const float*)d_in[9];
    const float* in2_w   = (const float*)d_in[10];
    const float* conv2_w = (const float*)d_in[11];
    const float* conv2_b = (const float*)d_in[12];
    const float* xp2_w   = (const float*)d_in[13];
    const float* dtp2_w  = (const float*)d_in[14];
    const float* dtp2_b  = (const float*)d_in[15];
    const float* Alog2   = (const float*)d_in[16];
    const float* D2      = (const float*)d_in[17];
    const float* outp2_w = (const float*)d_in[18];
    const float* c1_w    = (const float*)d_in[19];
    const float* c1_b    = (const float*)d_in[20];
    const float* c2_w    = (const float*)d_in[21];
    const float* c2_b    = (const float*)d_in[22];
    const float* ln1_g   = (const float*)d_in[23];
    const float* ln1_b   = (const float*)d_in[24];
    const float* ln2_g   = (const float*)d_in[25];
    const float* ln2_b   = (const float*)d_in[26];
    float* out = (float*)d_out;

    float *xz1,*xz2,*xdbl1,*xdbl2,*o,*xln,*yff;
    cudaGetSymbolAddress((void**)&xz1,  g_xz1);
    cudaGetSymbolAddress((void**)&xz2,  g_xz2);
    cudaGetSymbolAddress((void**)&xdbl1,g_xdbl1);
    cudaGetSymbolAddress((void**)&xdbl2,g_xdbl2);
    cudaGetSymbolAddress((void**)&o,    g_o);
    cudaGetSymbolAddress((void**)&xln,  g_xln);
    cudaGetSymbolAddress((void**)&yff,  g_yff);

    h16 *xh,*xc1h,*xc2h,*yh,*xlnh,*hffh;
    cudaGetSymbolAddress((void**)&xh,  g_xh);
    cudaGetSymbolAddress((void**)&xc1h,g_xc1h);
    cudaGetSymbolAddress((void**)&xc2h,g_xc2h);
    cudaGetSymbolAddress((void**)&yh,  g_yh);
    cudaGetSymbolAddress((void**)&xlnh,g_xlnh);
    cudaGetSymbolAddress((void**)&hffh,g_hffh);

    h16 *win1h,*win2h,*wxp1h,*wxp2h,*woh,*wc1h,*wc2h;
    cudaGetSymbolAddress((void**)&win1h,g_win1h);
    cudaGetSymbolAddress((void**)&win2h,g_win2h);
    cudaGetSymbolAddress((void**)&wxp1h,g_wxp1h);
    cudaGetSymbolAddress((void**)&wxp2h,g_wxp2h);
    cudaGetSymbolAddress((void**)&woh,  g_woh);
    cudaGetSymbolAddress((void**)&wc1h, g_wc1h);
    cudaGetSymbolAddress((void**)&wc2h, g_wc2h);

    // dyn smem: 4 stages x (A 10240 + B BN*80)
    const int SM128 = 4*(10240 + 10240);  // 81920
    const int SM64  = 4*(10240 + 5120);   // 61440
    cudaFuncSetAttribute(tgemm<128,0>, cudaFuncAttributeMaxDynamicSharedMemorySize, SM128);
    cudaFuncSetAttribute(tgemm<128,3>, cudaFuncAttributeMaxDynamicSharedMemorySize, SM128);
    cudaFuncSetAttribute(tgemm<128,4>, cudaFuncAttributeMaxDynamicSharedMemorySize, SM128);
    cudaFuncSetAttribute(tgemm<64,0>,  cudaFuncAttributeMaxDynamicSharedMemorySize, SM64);

    convert_all<<<(CV_TOTAL+255)/256,256>>>(x, in1_w, in2_w, xp1_w, xp2_w,
                                            outp1_w, outp2_w, c1_w, c2_w,
                                            Alog1, Alog2);

    // in_proj, both dirs in one launch: (8192x2048) = x @ W^T, K=512 -> fp32 xz
    {
        dim3 g(2*DIN/128, MROWS/128, 2);
        GArg a0 = {xh, win1h, xz1, nullptr};
        GArg a1 = {xh, win2h, xz2, nullptr};
        tgemm<128,0><<<g,256,SM128>>>(a0, a1, DM, DM, 2*DIN, DM, nullptr, nullptr);
    }

    // depthwise conv + silu (rolling window, fp32 in, fp16 out)
    {
        dim3 g(DIN/256, Lq/64, 16);
        conv_kernel<<<g,256>>>(conv1_w, conv1_b, conv2_w, conv2_b);
    }

    // x_proj, both dirs: (8192x64) = xc @ xp_w^T, K=1024
    {
        dim3 g(1, MROWS/128, 2);
        GArg a0 = {xc1h, wxp1h, xdbl1, nullptr};
        GArg a1 = {xc2h, wxp2h, xdbl2, nullptr};
        tgemm<64,0><<<g,128,SM64>>>(a0, a1, DIN, DIN, 64, DIN, nullptr, nullptr);
    }

    // dt_proj + softplus (tiled) -> fp16 dt
    {
        dim3 g(DIN/128, MROWS/128, 2);
        dtg_kernel<<<g,256>>>(dtp1_w, dtp2_w, dtp1_b, dtp2_b);
    }

    // selective scan + gate -> fp16 y
    {
        dim3 gs(1024, 2);
        scan_kernel<<<gs,64>>>(D1, D2);
    }

    // out_proj fused: o = [y1|y2](8192x2048) @ fused_w^T, K=2048
    {
        dim3 g(DM/128, MROWS/128, 1);
        GArg a0 = {yh, woh, o, nullptr};
        tgemm<128,0><<<g,256,SM128>>>(a0, a0, 2*DIN, 2*DIN, DM, 2*DIN, nullptr, nullptr);
    }

    // LN1: xln = LN(o + x)  (+ fp16 copy)
    ln_kernel<<<MROWS/8,256>>>(o, x, ln1_g, ln1_b, xln, xlnh);

    // FFN
    {
        dim3 g1(DFF/128, MROWS/128, 1);
        GArg a0 = {xlnh, wc1h, nullptr, hffh};
        tgemm<128,4><<<g1,256,SM128>>>(a0, a0, DM, DM, DFF, DM, c1_b, c1_b);
        dim3 g2(DM/128, MROWS/128, 1);
        GArg a2 = {hffh, wc2h, yff, nullptr};
        tgemm<128,3><<<g2,256,SM128>>>(a2, a2, DFF, DFF, DM, DFF, c2_b, c2_b);
    }

    // LN2: out = LN(xln + yff)
    ln_kernel<<<MROWS/8,256>>>(xln, yff, ln2_g, ln2_b, out, nullptr);
}

// round 15
// speedup vs baseline: 1.0777x; 1.0146x over previous
#include <cuda_runtime.h>
#include <cuda_fp16.h>
#include <math.h>
#include <stdint.h>

#define Bq   8
#define Lq   1024
#define DM   512
#define DIN  1024
#define DFF  2048
#define DS   16
#define DTR  32
#define MROWS (Bq*Lq)   /* 8192 token rows */

typedef __half h16;

// ---------------- fp32 scratch ----------------
__device__ float g_xz1 [MROWS*2*DIN];
__device__ float g_xz2 [MROWS*2*DIN];
__device__ float g_xdbl1[MROWS*64];
__device__ float g_xdbl2[MROWS*64];
__device__ float g_o   [MROWS*DM];
__device__ float g_xln [MROWS*DM];
__device__ float g_yff [MROWS*DM];
__device__ float g_A   [2*DIN*DS];     // -exp(Alog) * log2(e)

// ---------------- fp16 activations ----------------
__device__ h16 g_xh  [MROWS*DM];
__device__ h16 g_xc1h[MROWS*DIN];
__device__ h16 g_xc2h[MROWS*DIN];
__device__ h16 g_dt1h[MROWS*DIN];
__device__ h16 g_dt2h[MROWS*DIN];
__device__ h16 g_yh  [MROWS*2*DIN];    // [dir0 | dir1] per row
__device__ h16 g_xlnh[MROWS*DM];
__device__ h16 g_hffh[MROWS*DFF];

// ---------------- fp16 weights ----------------
__device__ h16 g_win1h[2*DIN*DM];
__device__ h16 g_win2h[2*DIN*DM];
__device__ h16 g_wxp1h[64*DIN];
__device__ h16 g_wxp2h[64*DIN];
__device__ h16 g_woh  [DM*2*DIN];      // fused [out1 | out2]
__device__ h16 g_wc1h [DFF*DM];
__device__ h16 g_wc2h [DM*DFF];

// ======================= helpers =======================
__device__ __forceinline__ float ex2(float x) {
    float r;
    asm("ex2.approx.f32 %0, %1;" : "=f"(r) : "f"(x));
    return r;
}
__device__ __forceinline__ uint32_t smem_u32(const void* p) {
    uint32_t a;
    asm("{ .reg .u64 t; cvta.to.shared.u64 t, %1; cvt.u32.u64 %0, t; }" : "=r"(a) : "l"(p));
    return a;
}
__device__ __forceinline__ void ldmx4(uint32_t* r, uint32_t addr) {
    asm volatile("ldmatrix.sync.aligned.m8n8.x4.shared.b16 {%0,%1,%2,%3}, [%4];"
                 : "=r"(r[0]), "=r"(r[1]), "=r"(r[2]), "=r"(r[3]) : "r"(addr));
}
__device__ __forceinline__ void ldmx2(uint32_t* r, uint32_t addr) {
    asm volatile("ldmatrix.sync.aligned.m8n8.x2.shared.b16 {%0,%1}, [%2];"
                 : "=r"(r[0]), "=r"(r[1]) : "r"(addr));
}
__device__ __forceinline__ void hmma(float* d, const uint32_t* a, const uint32_t* b) {
    asm volatile(
        "mma.sync.aligned.m16n8k16.row.col.f32.f16.f16.f32 "
        "{%0,%1,%2,%3}, {%4,%5,%6,%7}, {%8,%9}, {%0,%1,%2,%3};"
        : "+f"(d[0]), "+f"(d[1]), "+f"(d[2]), "+f"(d[3])
        : "r"(a[0]), "r"(a[1]), "r"(a[2]), "r"(a[3]), "r"(b[0]), "r"(b[1]));
}
__device__ __forceinline__ void cpa16(uint32_t dst, const void* src) {
    asm volatile("cp.async.cg.shared.global [%0], [%1], 16;" :: "r"(dst), "l"(src));
}
#define CP_COMMIT() asm volatile("cp.async.commit_group;" ::: "memory")
template<int N> __device__ __forceinline__ void cp_wait() {
    asm volatile("cp.async.wait_group %0;" :: "n"(N) : "memory");
}
__device__ __forceinline__ float gelu_exact(float x) {
    return 0.5f * x * (1.0f + erff(x * 0.70710678118654752f));
}

struct GArg { const h16* A; const h16* B; float* C; h16* Ch; };

// ======================= fp16 HMMA GEMM, 3-stage cp.async =======================
// C[m,n] = sum_k A[m,k]*B[n,k]; fp16 in, fp32 accum. blockIdx.z selects arg set.
// Block tile BM x BN, BK=32, warp tile 64x32.
// EPI: 0 = fp32 store, 3 = bias fp32, 4 = bias+GELU fp16 store.
template<int BM, int BN, int EPI>
__global__ __launch_bounds__(32*(BM/64)*(BN/32))
void tgemm(GArg g0, GArg g1, int lda, int ldb, int ldc, int K,
           const float* bias0, const float* bias1)
{
    constexpr int WM = BM / 64;
    constexpr int WN = BN / 32;
    constexpr int T  = 32 * WM * WN;
    constexpr int PK = 40;                    // padded k stride (elems), 80B
    constexpr int ASZ = BM * PK * 2;          // bytes
    constexpr int BSZ = BN * PK * 2;
    constexpr int STG = ASZ + BSZ;

    const GArg ga = blockIdx.z ? g1 : g0;
    const float* bias = blockIdx.z ? bias1 : bias0;

    extern __shared__ char smem[];
    const uint32_t base = smem_u32(smem);

    const int tid  = threadIdx.x;
    const int wid  = tid >> 5, lane = tid & 31;
    const int warp_m = wid % WM, warp_n = wid / WM;
    const int m0 = blockIdx.y * BM;
    const int n0 = blockIdx.x * BN;

    float acc[4][4][4];
#pragma unroll
    for (int i = 0; i < 4; i++)
#pragma unroll
        for (int j = 0; j < 4; j++)
#pragma unroll
            for (int q = 0; q < 4; q++) acc[i][j][q] = 0.f;

    const int rA = (lane & 15);
    const int cA = (lane >> 4) * 8;
    const int l2 = lane & 15;
    const int rB = l2 & 7;
    const int cB = (l2 >> 3) * 8;

    auto load_tiles = [&](int k0, uint32_t aS, uint32_t bS) {
#pragma unroll
        for (int m = 0; m < (BM * 4) / T; m++) {
            int cid = tid + m * T;
            int row = cid >> 2, c4 = cid & 3;
            cpa16(aS + (row * PK + c4 * 8) * 2,
                  ga.A + (size_t)(m0 + row) * lda + k0 + c4 * 8);
        }
#pragma unroll
        for (int m = 0; m < (BN * 4) / T; m++) {
            int cid = tid + m * T;
            int row = cid >> 2, c4 = cid & 3;
            cpa16(bS + (row * PK + c4 * 8) * 2,
                  ga.B + (size_t)(n0 + row) * ldb + k0 + c4 * 8);
        }
    };

    const int nk = K / 32;
    load_tiles(0, base, base + ASZ);
    CP_COMMIT();
    load_tiles(32, base + STG, base + STG + ASZ);
    CP_COMMIT();

    for (int i = 0; i < nk; i++) {
        if (i < nk - 1) cp_wait<1>(); else cp_wait<0>();
        __syncthreads();
        if (i + 2 < nk) {
            int s = (i + 2) % 3;
            load_tiles((i + 2) * 32, base + s * STG, base + s * STG + ASZ);
            CP_COMMIT();
        }
        const uint32_t aS = base + (i % 3) * STG;
        const uint32_t bS = aS + ASZ;

#pragma unroll
        for (int kk = 0; kk < 32; kk += 16) {
            uint32_t Ar[4][4], Br[4][2];
            const int aoff = kk + cA;
            const int boff = kk + cB;
#pragma unroll
            for (int mf = 0; mf < 4; mf++)
                ldmx4(Ar[mf], aS + ((warp_m*64 + mf*16 + rA) * PK + aoff) * 2);
#pragma unroll
            for (int nf = 0; nf < 4; nf++)
                ldmx2(Br[nf], bS + ((warp_n*32 + nf*8 + rB) * PK + boff) * 2);
#pragma unroll
            for (int mf = 0; mf < 4; mf++)
#pragma unroll
                for (int nf = 0; nf < 4; nf++)
                    hmma(acc[mf][nf], Ar[mf], Br[nf]);
        }
    }

    // ---- epilogue ----
    const int rr = lane >> 2;
    const int cc = (lane & 3) * 2;
#pragma unroll
    for (int mf = 0; mf < 4; mf++) {
#pragma unroll
        for (int nf = 0; nf < 4; nf++) {
            int col = n0 + warp_n*32 + nf*8 + cc;
            float b0 = 0.f, b1 = 0.f;
            if (EPI == 3 || EPI == 4) { b0 = bias[col]; b1 = bias[col+1]; }
#pragma unroll
            for (int h = 0; h < 2; h++) {
                int row = m0 + warp_m*64 + mf*16 + rr + h*8;
                float v0 = acc[mf][nf][h*2+0];
                float v1 = acc[mf][nf][h*2+1];
                if (EPI == 3) {
                    *reinterpret_cast<float2*>(ga.C + (size_t)row * ldc + col) =
                        make_float2(v0 + b0, v1 + b1);
                } else if (EPI == 4) {
                    v0 = gelu_exact(v0 + b0); v1 = gelu_exact(v1 + b1);
                    *reinterpret_cast<__half2*>(ga.Ch + (size_t)row * ldc + col) =
                        __floats2half2_rn(v0, v1);
                } else {
                    *reinterpret_cast<float2*>(ga.C + (size_t)row * ldc + col) =
                        make_float2(v0, v1);
                }
            }
        }
    }
}

// ---------------- single launch: all fp32->fp16 conversions + A prep ----------------
#define SZ_X   (MROWS*DM)
#define SZ_IN  (2*DIN*DM)
#define SZ_XP  (64*DIN)
#define SZ_OP  (DM*DIN)
#define SZ_C1  (DFF*DM)
#define SZ_C2  (DM*DFF)
#define SZ_A   (DIN*DS)
#define CV_TOTAL (SZ_X + 2*SZ_IN + 2*SZ_XP + 2*SZ_OP + SZ_C1 + SZ_C2 + 2*SZ_A)

__global__ void convert_all(const float* __restrict__ x,
                            const float* __restrict__ in1, const float* __restrict__ in2,
                            const float* __restrict__ xp1, const float* __restrict__ xp2,
                            const float* __restrict__ op1, const float* __restrict__ op2,
                            const float* __restrict__ c1,  const float* __restrict__ c2,
                            const float* __restrict__ Alog1, const float* __restrict__ Alog2)
{
    long j = (long)blockIdx.x*256 + threadIdx.x;
    if (j < SZ_X)  { g_xh[j] = __float2half_rn(x[j]); return; }    j -= SZ_X;
    if (j < SZ_IN) { g_win1h[j] = __float2half_rn(in1[j]); return; } j -= SZ_IN;
    if (j < SZ_IN) { g_win2h[j] = __float2half_rn(in2[j]); return; } j -= SZ_IN;
    if (j < SZ_XP) { g_wxp1h[j] = __float2half_rn(xp1[j]); return; } j -= SZ_XP;
    if (j < SZ_XP) { g_wxp2h[j] = __float2half_rn(xp2[j]); return; } j -= SZ_XP;
    if (j < SZ_OP) { long r = j/DIN, k = j%DIN;
                     g_woh[r*2*DIN + k] = __float2half_rn(op1[j]); return; } j -= SZ_OP;
    if (j < SZ_OP) { long r = j/DIN, k = j%DIN;
                     g_woh[r*2*DIN + DIN + k] = __float2half_rn(op2[j]); return; } j -= SZ_OP;
    if (j < SZ_C1) { g_wc1h[j] = __float2half_rn(c1[j]); return; } j -= SZ_C1;
    if (j < SZ_C2) { g_wc2h[j] = __float2half_rn(c2[j]); return; } j -= SZ_C2;
    if (j < SZ_A)  { g_A[j] = -__expf(Alog1[j]) * 1.44269504088896f; return; } j -= SZ_A;
    if (j < SZ_A)  { g_A[SZ_A + j] = -__expf(Alog2[j]) * 1.44269504088896f; }
}

// ---------------- depthwise causal conv (k=4) + bias + SiLU, rolling window -------------
// grid (DIN/256, Lq/64, 16): z = b + 8*dir. fp32 in, fp16 out (coalesced half stores).
__global__ __launch_bounds__(256)
void conv_kernel(const float* __restrict__ w1, const float* __restrict__ b1,
                 const float* __restrict__ w2, const float* __restrict__ b2)
{
    int d   = blockIdx.x*256 + threadIdx.x;
    int b   = blockIdx.z & 7;
    int dir = blockIdx.z >> 3;
    int T0  = blockIdx.y * 64;

    const float* xz = dir ? g_xz2 : g_xz1;
    const float* w  = dir ? w2 : w1;
    const float* cb = dir ? b2 : b1;
    h16* xch        = dir ? g_xc2h : g_xc1h;

    const float4 wv = *reinterpret_cast<const float4*>(w + d*4);
    const float bias = cb[d];
    const float* X = xz + ((size_t)b*Lq)*(2*DIN) + d;
    const size_t rs = 2*DIN;

    if (dir == 0) {
        float v0 = (T0-1 >= 0) ? X[(size_t)(T0-1)*rs] : 0.f;
        float v1 = (T0-2 >= 0) ? X[(size_t)(T0-2)*rs] : 0.f;
        float v2 = (T0-3 >= 0) ? X[(size_t)(T0-3)*rs] : 0.f;
#pragma unroll 4
        for (int t = T0; t < T0+64; t++) {
            float vn = X[(size_t)t*rs];
            float s = bias + wv.w*vn + wv.z*v0 + wv.y*v1 + wv.x*v2;
            v2 = v1; v1 = v0; v0 = vn;
            float r = s / (1.f + __expf(-s));
            xch[((size_t)b*Lq + t)*DIN + d] = __float2half_rn(r);
        }
    } else {
        float v0 = X[(size_t)T0*rs];
        float v1 = (T0+1 < Lq) ? X[(size_t)(T0+1)*rs] : 0.f;
        float v2 = (T0+2 < Lq) ? X[(size_t)(T0+2)*rs] : 0.f;
#pragma unroll 4
        for (int t = T0; t < T0+64; t++) {
            float vn = (t+3 < Lq) ? X[(size_t)(t+3)*rs] : 0.f;
            float s = bias + wv.w*v0 + wv.z*v1 + wv.y*v2 + wv.x*vn;
            v0 = v1; v1 = v2; v2 = vn;
            float r = s / (1.f + __expf(-s));
            xch[((size_t)b*Lq + t)*DIN + d] = __float2half_rn(r);
        }
    }
}

// ---------------- dt = softplus(xdbl[:, :32] @ W^T + b), tiled smem GEMM -> fp16 --------
__global__ __launch_bounds__(256)
void dtg_kernel(const float* __restrict__ w1, const float* __restrict__ w2,
                const float* __restrict__ b1, const float* __restrict__ b2)
{
    int dir = blockIdx.z;
    const float* xdbl = dir ? g_xdbl2 : g_xdbl1;
    const float* W    = dir ? w2 : w1;
    const float* bias = dir ? b2 : b1;
    h16* outp         = dir ? g_dt2h : g_dt1h;

    __shared__ float sX[128][33];
    __shared__ float sW[128][33];

    const int tid = threadIdx.x;
    const int d0 = blockIdx.x*128, r0 = blockIdx.y*128;

#pragma unroll
    for (int i = 0; i < 16; i++) {
        int idx = tid + i*256;
        int r = idx >> 5, k = idx & 31;
        sX[r][k] = xdbl[(size_t)(r0+r)*64 + k];
    }
#pragma unroll
    for (int i = 0; i < 16; i++) {
        int idx = tid + i*256;
        int dd = idx >> 5, k = idx & 31;
        sW[dd][k] = W[(size_t)(d0+dd)*DTR + k];
    }
    __syncthreads();

    const int tx = tid & 15, ty = tid >> 4;
    float acc[8][8];
#pragma unroll
    for (int i = 0; i < 8; i++)
#pragma unroll
        for (int j = 0; j < 8; j++) acc[i][j] = 0.f;

#pragma unroll
    for (int k = 0; k < 32; k++) {
        float a[8], bb[8];
#pragma unroll
        for (int i = 0; i < 8; i++) a[i] = sX[ty + i*16][k];
#pragma unroll
        for (int j = 0; j < 8; j++) bb[j] = sW[tx + j*16][k];
#pragma unroll
        for (int i = 0; i < 8; i++)
#pragma unroll
            for (int j = 0; j < 8; j++) acc[i][j] = fmaf(a[i], bb[j], acc[i][j]);
    }

#pragma unroll
    for (int i = 0; i < 8; i++) {
#pragma unroll
        for (int j = 0; j < 8; j++) {
            int r = r0 + ty + i*16, c = d0 + tx + j*16;
            float s = acc[i][j] + bias[c];
            float sp = (s > 20.f) ? s : log1pf(__expf(s));
            outp[(size_t)r*DIN + c] = __float2half_rn(sp);
        }
    }
}

// ---------------- selective scan (R6 structure + ex2, fp16 dt/u): ----------------------
// grid (1024, 2), 64 threads. 2 states/lane, 4 ch/warp, prefetch.
__global__ __launch_bounds__(64)
void scan_kernel(const float* __restrict__ D1, const float* __restrict__ D2)
{
    int dir = blockIdx.y;
    const h16*   dth  = dir ? g_dt2h : g_dt1h;
    const h16*   xch  = dir ? g_xc2h : g_xc1h;
    const float* xdbl = dir ? g_xdbl2: g_xdbl1;
    const float* xz   = dir ? g_xz2  : g_xz1;
    const float* Aexp = g_A + dir*DIN*DS;
    const float* Dv_  = dir ? D2 : D1;

    int warp = threadIdx.x >> 5, lane = threadIdx.x & 31;
    int sl  = lane & 7;                      // state lane (2 states each)
    int chl = lane >> 3;                     // channel within warp
    int c   = blockIdx.x*8 + warp*4 + chl;   // channels per dir: 8192
    int b   = c >> 10, d = c & (DIN-1);

    const float2 a2 = *(const float2*)(Aexp + d*DS + sl*2);
    const float Dd = Dv_[d];
    float hx = 0.f, hy = 0.f;
    const int rbase = b*Lq;
    const int step = dir ? -1 : 1;

    int t = dir ? (Lq-1) : 0;
    size_t row = rbase + t;
    float dtv = __half2float(dth[row*DIN + d]);
    float uv  = __half2float(xch[row*DIN + d]);
    float2 Bv = *(const float2*)(xdbl + row*64 + DTR + sl*2);
    float2 Cv = *(const float2*)(xdbl + row*64 + DTR + DS + sl*2);
    float zv  = xz[row*(2*DIN) + DIN + d];

    for (int i = 0; i < Lq; i++) {
        int tn = t + step;
        if (tn < 0) tn = 0; if (tn > Lq-1) tn = Lq-1;
        size_t rown = rbase + tn;
        // prefetch next
        float dtn = __half2float(dth[rown*DIN + d]);
        float un  = __half2float(xch[rown*DIN + d]);
        float2 Bn = *(const float2*)(xdbl + rown*64 + DTR + sl*2);
        float2 Cn = *(const float2*)(xdbl + rown*64 + DTR + DS + sl*2);
        float zn  = xz[rown*(2*DIN) + DIN + d];
        // compute current
        float du = dtv*uv;
        hx = fmaf(ex2(dtv*a2.x), hx, du*Bv.x);
        hy = fmaf(ex2(dtv*a2.y), hy, du*Bv.y);
        float p = hx*Cv.x + hy*Cv.y;
        p += __shfl_xor_sync(0xffffffffu, p, 1);
        p += __shfl_xor_sync(0xffffffffu, p, 2);
        p += __shfl_xor_sync(0xffffffffu, p, 4);
        if (sl == 0) {
            float yv = (p + uv*Dd) * (zv / (1.f + __expf(-zv)));
            g_yh[row*(2*DIN) + dir*DIN + d] = __float2half_rn(yv);
        }
        dtv = dtn; uv = un; Bv = Bn; Cv = Cn; zv = zn;
        t = tn; row = rown;
    }
}

// ---------------- LayerNorm: out = LN(a + b) * g + beta (+ optional fp16 copy) ---------
__global__ __launch_bounds__(256)
void ln_kernel(const float* __restrict__ a, const float* __restrict__ b,
               const float* __restrict__ g, const float* __restrict__ beta,
               float* __restrict__ out, h16* __restrict__ oh)
{
    int row  = blockIdx.x*8 + (threadIdx.x >> 5);
    int lane = threadIdx.x & 31;
    const float* pa = a + (size_t)row*DM;
    const float* pb = b + (size_t)row*DM;
    float v[16];
    float s = 0.f, s2 = 0.f;
#pragma unroll
    for (int i = 0; i < 16; i++) {
        int cix = lane + i*32;
        float x = pa[cix] + pb[cix];
        v[i] = x; s += x; s2 = fmaf(x, x, s2);
    }
#pragma unroll
    for (int off = 16; off > 0; off >>= 1) {
        s  += __shfl_xor_sync(0xffffffffu, s,  off);
        s2 += __shfl_xor_sync(0xffffffffu, s2, off);
    }
    float mean = s * (1.f/DM);
    float var  = s2 * (1.f/DM) - mean*mean;
    float inv  = rsqrtf(var + 1e-5f);
    float* po = out + (size_t)row*DM;
#pragma unroll
    for (int i = 0; i < 16; i++) {
        int cix = lane + i*32;
        float r = (v[i]-mean)*inv*g[cix] + beta[cix];
        po[cix] = r;
        if (oh) oh[(size_t)row*DM + cix] = __float2half_rn(r);
    }
}

// ---------------- launch ----------------
extern "C" void kernel_launch(void* const* d_in, const int* in_sizes, int n_in,
                              void* d_out, int out_size)
{
    const float* x       = (const float*)d_in[0];
    const float* in1_w   = (const float*)d_in[1];
    const float* conv1_w = (const float*)d_in[2];
    const float* conv1_b = (const float*)d_in[3];
    const float* xp1_w   = (const float*)d_in[4];
    const float* dtp1_w  = (const float*)d_in[5];
    const float* dtp1_b  = (const float*)d_in[6];
    const float* Alog1   = (const float*)d_in[7];
    const float* D1      = (const float*)d_in[8];
    const float* outp1_w = (const float*)d_in[9];
    const float* in2_w   = (const float*)d_in[10];
    const float* conv2_w = (const float*)d_in[11];
    const float* conv2_b = (const float*)d_in[12];
    const float* xp2_w   = (const float*)d_in[13];
    const float* dtp2_w  = (const float*)d_in[14];
    const float* dtp2_b  = (const float*)d_in[15];
    const float* Alog2   = (const float*)d_in[16];
    const float* D2      = (const float*)d_in[17];
    const float* outp2_w = (const float*)d_in[18];
    const float* c1_w    = (const float*)d_in[19];
    const float* c1_b    = (const float*)d_in[20];
    const float* c2_w    = (const float*)d_in[21];
    const float* c2_b    = (const float*)d_in[22];
    const float* ln1_g   = (const float*)d_in[23];
    const float* ln1_b   = (const float*)d_in[24];
    const float* ln2_g   = (const float*)d_in[25];
    const float* ln2_b   = (const float*)d_in[26];
    float* out = (float*)d_out;

    float *xz1,*xz2,*xdbl1,*xdbl2,*o,*xln,*yff;
    cudaGetSymbolAddress((void**)&xz1,  g_xz1);
    cudaGetSymbolAddress((void**)&xz2,  g_xz2);
    cudaGetSymbolAddress((void**)&xdbl1,g_xdbl1);
    cudaGetSymbolAddress((void**)&xdbl2,g_xdbl2);
    cudaGetSymbolAddress((void**)&o,    g_o);
    cudaGetSymbolAddress((void**)&xln,  g_xln);
    cudaGetSymbolAddress((void**)&yff,  g_yff);

    h16 *xh,*xc1h,*xc2h,*yh,*xlnh,*hffh;
    cudaGetSymbolAddress((void**)&xh,  g_xh);
    cudaGetSymbolAddress((void**)&xc1h,g_xc1h);
    cudaGetSymbolAddress((void**)&xc2h,g_xc2h);
    cudaGetSymbolAddress((void**)&yh,  g_yh);
    cudaGetSymbolAddress((void**)&xlnh,g_xlnh);
    cudaGetSymbolAddress((void**)&hffh,g_hffh);

    h16 *win1h,*win2h,*wxp1h,*wxp2h,*woh,*wc1h,*wc2h;
    cudaGetSymbolAddress((void**)&win1h,g_win1h);
    cudaGetSymbolAddress((void**)&win2h,g_win2h);
    cudaGetSymbolAddress((void**)&wxp1h,g_wxp1h);
    cudaGetSymbolAddress((void**)&wxp2h,g_wxp2h);
    cudaGetSymbolAddress((void**)&woh,  g_woh);
    cudaGetSymbolAddress((void**)&wc1h, g_wc1h);
    cudaGetSymbolAddress((void**)&wc2h, g_wc2h);

    // dyn smem: 3 stages x (BM*80 + BN*80)
    const int SM128 = 3*(10240 + 10240);  // 61440
    const int SM64  = 3*(5120 + 5120);    // 30720
    cudaFuncSetAttribute(tgemm<128,128,0>, cudaFuncAttributeMaxDynamicSharedMemorySize, SM128);
    cudaFuncSetAttribute(tgemm<128,128,3>, cudaFuncAttributeMaxDynamicSharedMemorySize, SM128);
    cudaFuncSetAttribute(tgemm<128,128,4>, cudaFuncAttributeMaxDynamicSharedMemorySize, SM128);
    cudaFuncSetAttribute(tgemm<64,64,0>,   cudaFuncAttributeMaxDynamicSharedMemorySize, SM64);

    convert_all<<<(CV_TOTAL+255)/256,256>>>(x, in1_w, in2_w, xp1_w, xp2_w,
                                            outp1_w, outp2_w, c1_w, c2_w,
                                            Alog1, Alog2);

    // in_proj, both dirs in one launch: (8192x2048) = x @ W^T, K=512 -> fp32 xz
    {
        dim3 g(2*DIN/128, MROWS/128, 2);
        GArg a0 = {xh, win1h, xz1, nullptr};
        GArg a1 = {xh, win2h, xz2, nullptr};
        tgemm<128,128,0><<<g,256,SM128>>>(a0, a1, DM, DM, 2*DIN, DM, nullptr, nullptr);
    }

    // depthwise conv + silu (rolling window, fp32 in, fp16 out)
    {
        dim3 g(DIN/256, Lq/64, 16);
        conv_kernel<<<g,256>>>(conv1_w, conv1_b, conv2_w, conv2_b);
    }

    // x_proj, both dirs: (8192x64) = xc @ xp_w^T, K=1024 (BM=64: 256 blocks, high occ)
    {
        dim3 g(1, MROWS/64, 2);
        GArg a0 = {xc1h, wxp1h, xdbl1, nullptr};
        GArg a1 = {xc2h, wxp2h, xdbl2, nullptr};
        tgemm<64,64,0><<<g,64,SM64>>>(a0, a1, DIN, DIN, 64, DIN, nullptr, nullptr);
    }

    // dt_proj + softplus (tiled) -> fp16 dt
    {
        dim3 g(DIN/128, MROWS/128, 2);
        dtg_kernel<<<g,256>>>(dtp1_w, dtp2_w, dtp1_b, dtp2_b);
    }

    // selective scan + gate -> fp16 y
    {
        dim3 gs(1024, 2);
        scan_kernel<<<gs,64>>>(D1, D2);
    }

    // out_proj fused: o = [y1|y2](8192x2048) @ fused_w^T, K=2048
    {
        dim3 g(DM/128, MROWS/128, 1);
        GArg a0 = {yh, woh, o, nullptr};
        tgemm<128,128,0><<<g,256,SM128>>>(a0, a0, 2*DIN, 2*DIN, DM, 2*DIN, nullptr, nullptr);
    }

    // LN1: xln = LN(o + x)  (+ fp16 copy)
    ln_kernel<<<MROWS/8,256>>>(o, x, ln1_g, ln1_b, xln, xlnh);

    // FFN
    {
        dim3 g1(DFF/128, MROWS/128, 1);
        GArg a0 = {xlnh, wc1h, nullptr, hffh};
        tgemm<128,128,4><<<g1,256,SM128>>>(a0, a0, DM, DM, DFF, DM, c1_b, c1_b);
        dim3 g2(DM/128, MROWS/128, 1);
        GArg a2 = {hffh, wc2h, yff, nullptr};
        tgemm<128,128,3><<<g2,256,SM128>>>(a2, a2, DFF, DFF, DM, DFF, c2_b, c2_b);
    }

    // LN2: out = LN(xln + yff)
    ln_kernel<<<MROWS/8,256>>>(xln, yff, ln2_g, ln2_b, out, nullptr);
}